// round 1
// baseline (speedup 1.0000x reference)
#include <cuda_runtime.h>

#define SQ 4096
#define DMODEL 768
#define NH 12
#define NB 32
#define GQ 16
#define BATCH 2
#define QSZ (BATCH*NH*SQ*64)     // 6291456 floats
#define OFF_Q 0
#define OFF_K (1*QSZ)
#define OFF_V (2*QSZ)
#define OFF_KG (3*QSZ)
#define OFF_VG (4*QSZ)
#define OFF_MERGED (5*QSZ)       // B*S*D = 6291456 floats too

__device__ float g_scratch[6 * QSZ];

// ---------------------------------------------------------------------------
// Classic 128x128x8 register-blocked SGEMM. A:[M,K] row-major, W:[K,N] row-major.
// ---------------------------------------------------------------------------
struct PArgs {
    const float* W[5];
    const float* bias[5];
    long         dstOff[5];
    float        scale[5];
};

// Projection GEMM: out layout [B,H,S,DH] (head-split), z picks which projection.
__global__ __launch_bounds__(256) void sgemm_proj(const float* __restrict__ A, PArgs p)
{
    const int z = blockIdx.z;
    const float* __restrict__ Bw   = p.W[z];
    const float* __restrict__ bias = p.bias[z];
    float* __restrict__ dst        = g_scratch + p.dstOff[z];
    const float scale = p.scale[z];
    const int K = DMODEL, N = DMODEL;

    __shared__ float As[8][128];
    __shared__ float Bs[8][128];

    const int tid  = threadIdx.x;
    const int row0 = blockIdx.y * 128, col0 = blockIdx.x * 128;
    const int arow = tid >> 1, acol = (tid & 1) << 2;
    const int brow = tid >> 5, bcol = (tid & 31) << 2;
    const float* Ap = A  + (size_t)(row0 + arow) * K + acol;
    const float* Bp = Bw + (size_t)brow * N + col0 + bcol;

    float acc[8][8];
#pragma unroll
    for (int i = 0; i < 8; i++)
#pragma unroll
        for (int j = 0; j < 8; j++) acc[i][j] = 0.f;

    const int tr = (tid >> 4) << 3;
    const int tc = (tid & 15) << 3;

    for (int k0 = 0; k0 < K; k0 += 8) {
        float4 a4 = *(const float4*)Ap;
        As[acol + 0][arow] = a4.x;
        As[acol + 1][arow] = a4.y;
        As[acol + 2][arow] = a4.z;
        As[acol + 3][arow] = a4.w;
        *(float4*)&Bs[brow][bcol] = *(const float4*)Bp;
        __syncthreads();
        Ap += 8;
        Bp += (size_t)8 * N;
#pragma unroll
        for (int kk = 0; kk < 8; kk++) {
            float rm[8], rn[8];
#pragma unroll
            for (int i = 0; i < 8; i++) rm[i] = As[kk][tr + i];
#pragma unroll
            for (int j = 0; j < 8; j++) rn[j] = Bs[kk][tc + j];
#pragma unroll
            for (int i = 0; i < 8; i++)
#pragma unroll
                for (int j = 0; j < 8; j++) acc[i][j] += rm[i] * rn[j];
        }
        __syncthreads();
    }

#pragma unroll
    for (int i = 0; i < 8; i++) {
        const int m = row0 + tr + i;
        const int b = m >> 12, s = m & (SQ - 1);
#pragma unroll
        for (int j = 0; j < 8; j++) {
            const int n = col0 + tc + j;
            const float v = (acc[i][j] + bias[n]) * scale;
            const int h = n >> 6, d = n & 63;
            dst[((((size_t)b * NH + h) * SQ + s) << 6) + d] = v;
        }
    }
}

// Output GEMM: plain row-major out [M,N]
__global__ __launch_bounds__(256) void sgemm_out(const float* __restrict__ Bw,
                                                 const float* __restrict__ bias,
                                                 float* __restrict__ dst)
{
    const float* __restrict__ A = g_scratch + OFF_MERGED;
    const int K = DMODEL, N = DMODEL;

    __shared__ float As[8][128];
    __shared__ float Bs[8][128];

    const int tid  = threadIdx.x;
    const int row0 = blockIdx.y * 128, col0 = blockIdx.x * 128;
    const int arow = tid >> 1, acol = (tid & 1) << 2;
    const int brow = tid >> 5, bcol = (tid & 31) << 2;
    const float* Ap = A  + (size_t)(row0 + arow) * K + acol;
    const float* Bp = Bw + (size_t)brow * N + col0 + bcol;

    float acc[8][8];
#pragma unroll
    for (int i = 0; i < 8; i++)
#pragma unroll
        for (int j = 0; j < 8; j++) acc[i][j] = 0.f;

    const int tr = (tid >> 4) << 3;
    const int tc = (tid & 15) << 3;

    for (int k0 = 0; k0 < K; k0 += 8) {
        float4 a4 = *(const float4*)Ap;
        As[acol + 0][arow] = a4.x;
        As[acol + 1][arow] = a4.y;
        As[acol + 2][arow] = a4.z;
        As[acol + 3][arow] = a4.w;
        *(float4*)&Bs[brow][bcol] = *(const float4*)Bp;
        __syncthreads();
        Ap += 8;
        Bp += (size_t)8 * N;
#pragma unroll
        for (int kk = 0; kk < 8; kk++) {
            float rm[8], rn[8];
#pragma unroll
            for (int i = 0; i < 8; i++) rm[i] = As[kk][tr + i];
#pragma unroll
            for (int j = 0; j < 8; j++) rn[j] = Bs[kk][tc + j];
#pragma unroll
            for (int i = 0; i < 8; i++)
#pragma unroll
                for (int j = 0; j < 8; j++) acc[i][j] += rm[i] * rn[j];
        }
        __syncthreads();
    }

#pragma unroll
    for (int i = 0; i < 8; i++) {
        const int m = row0 + tr + i;
#pragma unroll
        for (int j = 0; j < 8; j++) {
            const int n = col0 + tc + j;
            dst[(size_t)m * N + n] = acc[i][j] + bias[n];
        }
    }
}

// ---------------------------------------------------------------------------
// Local (banded) attention + global-key columns, flash-style online softmax.
// One block per (b, h, n); one thread per query row. Writes merged [B,S,D].
// ---------------------------------------------------------------------------
__global__ __launch_bounds__(128) void local_attn(const int* __restrict__ mask)
{
    __shared__ float ks[64 * 64];
    __shared__ float vs[64 * 64];
    __shared__ float gks[GQ * 64];
    __shared__ float gvs[GQ * 64];
    __shared__ unsigned char okc[64];
    __shared__ unsigned char okg[GQ];

    const float* __restrict__ gq = g_scratch + OFF_Q;
    const float* __restrict__ gk = g_scratch + OFF_K;
    const float* __restrict__ gv = g_scratch + OFF_V;
    float* __restrict__ merged   = g_scratch + OFF_MERGED;

    const int blk = blockIdx.x;
    const int n = blk & (NB - 1);
    const int h = (blk >> 5) % NH;
    const int b = blk / (NB * NH);
    const int tid = threadIdx.x;
    const int s = (n << 7) + tid;
    const size_t bh = (size_t)(b * NH + h);

    // load this thread's q row (64 floats) into registers
    float q[64];
    {
        const float* qrow = gq + ((bh << 12) + s) * 64;
#pragma unroll
        for (int i = 0; i < 16; i++) {
            float4 t = *(const float4*)(qrow + 4 * i);
            q[4 * i + 0] = t.x; q[4 * i + 1] = t.y;
            q[4 * i + 2] = t.z; q[4 * i + 3] = t.w;
        }
    }

    // preload global K/V (first G positions of regular k/v)
    for (int idx = tid; idx < GQ * 64; idx += 128) {
        const int g = idx >> 6, d = idx & 63;
        gks[idx] = gk[((bh << 12) + g) * 64 + d];
        gvs[idx] = gv[((bh << 12) + g) * 64 + d];
    }
    if (tid < GQ) okg[tid] = (unsigned char)(mask[b * SQ + tid] != 0);

    float m = -1e30f, l = 0.f;
    float acc[64];
#pragma unroll
    for (int i = 0; i < 64; i++) acc[i] = 0.f;

    const int base0 = (n << 7) - 128;
    for (int c = 0; c < 6; c++) {
        const int basec = base0 + (c << 6);
        __syncthreads();
        // cooperative chunk load: 64 keys x 64 dims for K and V
        {
            const int j = tid >> 1, half = tid & 1;
            const int orig = basec + j;
            const bool inr = (orig >= 0) && (orig < SQ);
            float* ksd = ks + j * 64 + (half << 5);
            float* vsd = vs + j * 64 + (half << 5);
            if (inr) {
                const float* kr = gk + ((bh << 12) + orig) * 64 + (half << 5);
                const float* vr = gv + ((bh << 12) + orig) * 64 + (half << 5);
#pragma unroll
                for (int ii = 0; ii < 8; ii++) {
                    *(float4*)(ksd + 4 * ii) = *(const float4*)(kr + 4 * ii);
                    *(float4*)(vsd + 4 * ii) = *(const float4*)(vr + 4 * ii);
                }
            } else {
#pragma unroll
                for (int ii = 0; ii < 8; ii++) {
                    *(float4*)(ksd + 4 * ii) = make_float4(0, 0, 0, 0);
                    *(float4*)(vsd + 4 * ii) = make_float4(0, 0, 0, 0);
                }
            }
            if (half == 0)
                okc[j] = (unsigned char)(inr && orig >= GQ && mask[b * SQ + (inr ? orig : 0)] != 0);
        }
        __syncthreads();

#pragma unroll 1
        for (int j = 0; j < 64; j++) {
            const int orig = basec + j;
            const int rel = orig - s;
            if (!okc[j] || rel > 128 || rel < -128) continue;
            float sc = 0.f;
            const float* kj = ks + j * 64;
#pragma unroll
            for (int dd = 0; dd < 16; dd++) {
                float4 kv = *(const float4*)(kj + 4 * dd);
                sc += q[4 * dd + 0] * kv.x + q[4 * dd + 1] * kv.y
                    + q[4 * dd + 2] * kv.z + q[4 * dd + 3] * kv.w;
            }
            float p;
            if (sc > m) {
                const float corr = __expf(m - sc);
                l *= corr;
#pragma unroll
                for (int dd = 0; dd < 64; dd++) acc[dd] *= corr;
                m = sc;
                p = 1.f;
            } else {
                p = __expf(sc - m);
            }
            l += p;
            const float* vj = vs + j * 64;
#pragma unroll
            for (int dd = 0; dd < 16; dd++) {
                float4 vv = *(const float4*)(vj + 4 * dd);
                acc[4 * dd + 0] += p * vv.x;
                acc[4 * dd + 1] += p * vv.y;
                acc[4 * dd + 2] += p * vv.z;
                acc[4 * dd + 3] += p * vv.w;
            }
        }
    }

    // global-key columns (same softmax row)
#pragma unroll 1
    for (int j = 0; j < GQ; j++) {
        if (!okg[j]) continue;
        float sc = 0.f;
        const float* kj = gks + j * 64;
#pragma unroll
        for (int dd = 0; dd < 16; dd++) {
            float4 kv = *(const float4*)(kj + 4 * dd);
            sc += q[4 * dd + 0] * kv.x + q[4 * dd + 1] * kv.y
                + q[4 * dd + 2] * kv.z + q[4 * dd + 3] * kv.w;
        }
        float p;
        if (sc > m) {
            const float corr = __expf(m - sc);
            l *= corr;
#pragma unroll
            for (int dd = 0; dd < 64; dd++) acc[dd] *= corr;
            m = sc;
            p = 1.f;
        } else {
            p = __expf(sc - m);
        }
        l += p;
        const float* vj = gvs + j * 64;
#pragma unroll
        for (int dd = 0; dd < 16; dd++) {
            float4 vv = *(const float4*)(vj + 4 * dd);
            acc[4 * dd + 0] += p * vv.x;
            acc[4 * dd + 1] += p * vv.y;
            acc[4 * dd + 2] += p * vv.z;
            acc[4 * dd + 3] += p * vv.w;
        }
    }

    const float inv = 1.f / l;
    float* orow = merged + ((size_t)b * SQ + s) * DMODEL + h * 64;
#pragma unroll
    for (int dd = 0; dd < 16; dd++) {
        float4 o;
        o.x = acc[4 * dd + 0] * inv;
        o.y = acc[4 * dd + 1] * inv;
        o.z = acc[4 * dd + 2] * inv;
        o.w = acc[4 * dd + 3] * inv;
        *(float4*)(orow + 4 * dd) = o;
    }
}

// ---------------------------------------------------------------------------
// Global-query attention: rows s < G are replaced by softmax(qg @ kg^T) @ vg.
// One block per (b, h, g). Also computes qg projection inline (tiny).
// ---------------------------------------------------------------------------
__global__ __launch_bounds__(128) void global_attn(const float* __restrict__ x,
                                                   const int* __restrict__ mask,
                                                   const float* __restrict__ Wqg,
                                                   const float* __restrict__ bqg)
{
    __shared__ float xs[DMODEL];
    __shared__ float qs[64];
    __shared__ float part[128];
    __shared__ float sc[SQ];
    __shared__ float red[4];

    const float* __restrict__ kgp = g_scratch + OFF_KG;
    const float* __restrict__ vgp = g_scratch + OFF_VG;
    float* __restrict__ merged    = g_scratch + OFF_MERGED;

    const int blk = blockIdx.x;
    const int g = blk & (GQ - 1);
    const int h = (blk >> 4) % NH;
    const int b = blk / (GQ * NH);
    const int tid = threadIdx.x;
    const size_t bh = (size_t)(b * NH + h);

    for (int i = tid; i < DMODEL; i += 128)
        xs[i] = x[((size_t)b * SQ + g) * DMODEL + i];
    __syncthreads();

    // qg[d] = scale * (bqg + xs @ Wqg[:, h*64+d])
    {
        const int d = tid & 63, half = tid >> 6;
        float a = 0.f;
        const float* wp = Wqg + (size_t)(half * 384) * DMODEL + h * 64 + d;
#pragma unroll 4
        for (int i = 0; i < 384; i++) a += xs[half * 384 + i] * wp[(size_t)i * DMODEL];
        part[tid] = a;
    }
    __syncthreads();
    if (tid < 64) qs[tid] = (part[tid] + part[tid + 64] + bqg[h * 64 + tid]) * 0.125f;
    __syncthreads();

    // scores over all S keys
    float lmax = -1e30f;
    for (int key = tid; key < SQ; key += 128) {
        const float* kr = kgp + ((bh << 12) + key) * 64;
        float d0 = 0.f;
#pragma unroll
        for (int dd = 0; dd < 16; dd++) {
            float4 kv = *(const float4*)(kr + 4 * dd);
            d0 += qs[4 * dd + 0] * kv.x + qs[4 * dd + 1] * kv.y
                + qs[4 * dd + 2] * kv.z + qs[4 * dd + 3] * kv.w;
        }
        const float v = (mask[b * SQ + key] != 0) ? d0 : -1e9f;
        sc[key] = v;
        lmax = fmaxf(lmax, v);
    }
#pragma unroll
    for (int o = 16; o; o >>= 1) lmax = fmaxf(lmax, __shfl_xor_sync(0xffffffffu, lmax, o));
    if ((tid & 31) == 0) red[tid >> 5] = lmax;
    __syncthreads();
    const float bmax = fmaxf(fmaxf(red[0], red[1]), fmaxf(red[2], red[3]));

    float ls = 0.f;
    for (int key = tid; key < SQ; key += 128) {
        const float e = __expf(sc[key] - bmax);
        sc[key] = e;
        ls += e;
    }
#pragma unroll
    for (int o = 16; o; o >>= 1) ls += __shfl_xor_sync(0xffffffffu, ls, o);
    __syncthreads();
    if ((tid & 31) == 0) red[tid >> 5] = ls;
    __syncthreads();
    const float bsum = red[0] + red[1] + red[2] + red[3];

    // PV: split keys across the two halves of the block
    {
        const int d = tid & 63, half = tid >> 6;
        float a = 0.f;
        const float* vp = vgp + ((bh << 12) + half * 2048) * 64 + d;
        const float* sp = sc + half * 2048;
#pragma unroll 4
        for (int key = 0; key < 2048; key++) a += sp[key] * vp[(size_t)key * 64];
        part[tid] = a;
    }
    __syncthreads();
    if (tid < 64) {
        const float o = (part[tid] + part[tid + 64]) / bsum;
        merged[((size_t)b * SQ + g) * DMODEL + h * 64 + tid] = o;
    }
}

// ---------------------------------------------------------------------------
extern "C" void kernel_launch(void* const* d_in, const int* in_sizes, int n_in,
                              void* d_out, int out_size)
{
    const float* x    = (const float*)d_in[0];
    const int*   mask = (const int*)d_in[1];
    const float* Wq   = (const float*)d_in[2];
    const float* bq   = (const float*)d_in[3];
    const float* Wk   = (const float*)d_in[4];
    const float* bk   = (const float*)d_in[5];
    const float* Wv   = (const float*)d_in[6];
    const float* bv   = (const float*)d_in[7];
    const float* Wqg  = (const float*)d_in[8];
    const float* bqg  = (const float*)d_in[9];
    const float* Wkg  = (const float*)d_in[10];
    const float* bkg  = (const float*)d_in[11];
    const float* Wvg  = (const float*)d_in[12];
    const float* bvg  = (const float*)d_in[13];
    const float* Wo   = (const float*)d_in[14];
    const float* bo   = (const float*)d_in[15];
    float* out = (float*)d_out;

    PArgs p;
    p.W[0] = Wq;  p.bias[0] = bq;  p.dstOff[0] = OFF_Q;  p.scale[0] = 0.125f;
    p.W[1] = Wk;  p.bias[1] = bk;  p.dstOff[1] = OFF_K;  p.scale[1] = 1.f;
    p.W[2] = Wv;  p.bias[2] = bv;  p.dstOff[2] = OFF_V;  p.scale[2] = 1.f;
    p.W[3] = Wkg; p.bias[3] = bkg; p.dstOff[3] = OFF_KG; p.scale[3] = 1.f;
    p.W[4] = Wvg; p.bias[4] = bvg; p.dstOff[4] = OFF_VG; p.scale[4] = 1.f;

    // 5 projections in one z-batched launch: M=8192, N=768, K=768
    dim3 gridP(DMODEL / 128, (BATCH * SQ) / 128, 5);
    sgemm_proj<<<gridP, 256>>>(x, p);

    // local banded attention (+ global-key columns) -> merged
    local_attn<<<BATCH * NH * NB, 128>>>(mask);

    // global-query rows overwrite merged[:, :G, :]
    global_attn<<<BATCH * NH * GQ, 128>>>(x, mask, Wqg, bqg);

    // output projection
    dim3 gridO(DMODEL / 128, (BATCH * SQ) / 128);
    sgemm_out<<<gridO, 256>>>(Wo, bo, out);
}

// round 2
// speedup vs baseline: 1.7827x; 1.7827x over previous
#include <cuda_runtime.h>
#include <cstdint>

#define SQ 4096
#define DMODEL 768
#define NH 12
#define NB 32
#define GQ 16
#define BATCH 2
#define QSZ (BATCH*NH*SQ*64)     // 6291456 floats
#define OFF_Q 0
#define OFF_K (1*QSZ)
#define OFF_V (2*QSZ)
#define OFF_KG (3*QSZ)
#define OFF_VG (4*QSZ)
#define OFF_MERGED (5*QSZ)       // B*S*D = 6291456 floats too

__device__ float g_scratch[6 * QSZ];

#define CP_ASYNC16(dst_u32, src) \
    asm volatile("cp.async.cg.shared.global [%0], [%1], 16;\n" :: "r"(dst_u32), "l"(src))

__device__ __forceinline__ uint32_t f2tf32(float f) {
    uint32_t u;
    asm("cvt.rna.tf32.f32 %0, %1;" : "=r"(u) : "f"(f));
    return u;
}

// ---------------------------------------------------------------------------
// tf32 tensor-core GEMM core: 128x128 block tile, 8 warps (4x2), warp 32x64,
// K chunk 16 (two k-steps of 8), cp.async double-buffered SMEM.
// A:[M,768] row-major tile at row0; Bw:[768,768] row-major tile at col0.
// Accumulators: acc[i(2)][j(8)][4] per thread.
// ---------------------------------------------------------------------------
struct SmemGemm {
    float As[2][128][20];   // [buf][m][k]  (pad 20 -> conflict-free frag loads)
    float Bs[2][16][136];   // [buf][k][n]  (pad 136 -> conflict-free frag loads)
};

__device__ __forceinline__ void gemm_tf32_core(
    const float* __restrict__ A, const float* __restrict__ Bw,
    int row0, int col0, SmemGemm& sm, float acc[2][8][4])
{
    const int tid  = threadIdx.x;
    const int lane = tid & 31, warp = tid >> 5;
    const int wm = (warp & 3) * 32, wn = (warp >> 2) * 64;
    const int g = lane >> 2, tg = lane & 3;

    const int ar = tid >> 2;          // 0..63 (A tile row, 2 passes)
    const int ac = (tid & 3) << 2;    // col4
    const int br = tid >> 5;          // 0..7 (B tile row, 2 passes)
    const int bc = (tid & 31) << 2;

    // prologue: tile 0
    {
#pragma unroll
        for (int it = 0; it < 2; it++) {
            const float* src = A + (size_t)(row0 + ar + it * 64) * DMODEL + ac;
            uint32_t dst = (uint32_t)__cvta_generic_to_shared(&sm.As[0][ar + it * 64][ac]);
            CP_ASYNC16(dst, src);
        }
#pragma unroll
        for (int it = 0; it < 2; it++) {
            const float* src = Bw + (size_t)(br + it * 8) * DMODEL + col0 + bc;
            uint32_t dst = (uint32_t)__cvta_generic_to_shared(&sm.Bs[0][br + it * 8][bc]);
            CP_ASYNC16(dst, src);
        }
        asm volatile("cp.async.commit_group;\n");
    }

    const int NT = DMODEL / 16;  // 48
    for (int kt = 0; kt < NT; kt++) {
        const int buf = kt & 1;
        if (kt + 1 < NT) {
            const int k0 = (kt + 1) * 16;
#pragma unroll
            for (int it = 0; it < 2; it++) {
                const float* src = A + (size_t)(row0 + ar + it * 64) * DMODEL + k0 + ac;
                uint32_t dst = (uint32_t)__cvta_generic_to_shared(&sm.As[buf ^ 1][ar + it * 64][ac]);
                CP_ASYNC16(dst, src);
            }
#pragma unroll
            for (int it = 0; it < 2; it++) {
                const float* src = Bw + (size_t)(k0 + br + it * 8) * DMODEL + col0 + bc;
                uint32_t dst = (uint32_t)__cvta_generic_to_shared(&sm.Bs[buf ^ 1][br + it * 8][bc]);
                CP_ASYNC16(dst, src);
            }
            asm volatile("cp.async.commit_group;\n");
            asm volatile("cp.async.wait_group 1;\n");
        } else {
            asm volatile("cp.async.wait_group 0;\n");
        }
        __syncthreads();

#pragma unroll
        for (int kk = 0; kk < 16; kk += 8) {
            uint32_t af[2][4];
#pragma unroll
            for (int i = 0; i < 2; i++) {
                const int m = wm + i * 16 + g;
                af[i][0] = f2tf32(sm.As[buf][m][kk + tg]);
                af[i][1] = f2tf32(sm.As[buf][m + 8][kk + tg]);
                af[i][2] = f2tf32(sm.As[buf][m][kk + tg + 4]);
                af[i][3] = f2tf32(sm.As[buf][m + 8][kk + tg + 4]);
            }
            uint32_t bf[8][2];
#pragma unroll
            for (int j = 0; j < 8; j++) {
                const int n = wn + j * 8 + g;
                bf[j][0] = f2tf32(sm.Bs[buf][kk + tg][n]);
                bf[j][1] = f2tf32(sm.Bs[buf][kk + tg + 4][n]);
            }
#pragma unroll
            for (int i = 0; i < 2; i++)
#pragma unroll
                for (int j = 0; j < 8; j++)
                    asm volatile(
                        "mma.sync.aligned.m16n8k8.row.col.f32.tf32.tf32.f32 "
                        "{%0,%1,%2,%3}, {%4,%5,%6,%7}, {%8,%9}, {%0,%1,%2,%3};\n"
                        : "+f"(acc[i][j][0]), "+f"(acc[i][j][1]),
                          "+f"(acc[i][j][2]), "+f"(acc[i][j][3])
                        : "r"(af[i][0]), "r"(af[i][1]), "r"(af[i][2]), "r"(af[i][3]),
                          "r"(bf[j][0]), "r"(bf[j][1]));
        }
        __syncthreads();
    }
}

// ---------------------------------------------------------------------------
struct PArgs {
    const float* W[5];
    const float* bias[5];
    long         dstOff[5];
    float        scale[5];
};

// Projection GEMM: out layout [B,H,S,DH] (head-split), z picks which projection.
__global__ __launch_bounds__(256) void mma_proj(const float* __restrict__ A, PArgs p)
{
    __shared__ SmemGemm sm;
    const int z = blockIdx.z;
    const float* __restrict__ Bw   = p.W[z];
    const float* __restrict__ bias = p.bias[z];
    float* __restrict__ dst        = g_scratch + p.dstOff[z];
    const float scale = p.scale[z];

    const int row0 = blockIdx.y * 128, col0 = blockIdx.x * 128;
    float acc[2][8][4];
#pragma unroll
    for (int i = 0; i < 2; i++)
#pragma unroll
        for (int j = 0; j < 8; j++)
#pragma unroll
            for (int c = 0; c < 4; c++) acc[i][j][c] = 0.f;

    gemm_tf32_core(A, Bw, row0, col0, sm, acc);

    const int tid = threadIdx.x;
    const int lane = tid & 31, warp = tid >> 5;
    const int wm = (warp & 3) * 32, wn = (warp >> 2) * 64;
    const int g = lane >> 2, tg = lane & 3;

#pragma unroll
    for (int i = 0; i < 2; i++) {
#pragma unroll
        for (int j = 0; j < 8; j++) {
            const int n0 = col0 + wn + j * 8 + 2 * tg;
#pragma unroll
            for (int c = 0; c < 4; c++) {
                const int r = row0 + wm + i * 16 + g + ((c >> 1) << 3);
                const int n = n0 + (c & 1);
                const int b = r >> 12, s = r & (SQ - 1);
                const int h = n >> 6, d = n & 63;
                const float v = (acc[i][j][c] + bias[n]) * scale;
                dst[((((size_t)b * NH + h) * SQ + s) << 6) + d] = v;
            }
        }
    }
}

// Output GEMM: plain row-major out [M,N]
__global__ __launch_bounds__(256) void mma_out(const float* __restrict__ Bw,
                                               const float* __restrict__ bias,
                                               float* __restrict__ dst)
{
    __shared__ SmemGemm sm;
    const float* __restrict__ A = g_scratch + OFF_MERGED;

    const int row0 = blockIdx.y * 128, col0 = blockIdx.x * 128;
    float acc[2][8][4];
#pragma unroll
    for (int i = 0; i < 2; i++)
#pragma unroll
        for (int j = 0; j < 8; j++)
#pragma unroll
            for (int c = 0; c < 4; c++) acc[i][j][c] = 0.f;

    gemm_tf32_core(A, Bw, row0, col0, sm, acc);

    const int tid = threadIdx.x;
    const int lane = tid & 31, warp = tid >> 5;
    const int wm = (warp & 3) * 32, wn = (warp >> 2) * 64;
    const int g = lane >> 2, tg = lane & 3;

#pragma unroll
    for (int i = 0; i < 2; i++) {
#pragma unroll
        for (int j = 0; j < 8; j++) {
            const int n0 = col0 + wn + j * 8 + 2 * tg;
#pragma unroll
            for (int c = 0; c < 4; c++) {
                const int r = row0 + wm + i * 16 + g + ((c >> 1) << 3);
                const int n = n0 + (c & 1);
                dst[(size_t)r * DMODEL + n] = acc[i][j][c] + bias[n];
            }
        }
    }
}

// ---------------------------------------------------------------------------
// Local (banded) attention + global-key columns, flash-style online softmax.
// One block per (b, h, n); one thread per query row. Writes merged [B,S,D].
// ---------------------------------------------------------------------------
__global__ __launch_bounds__(128) void local_attn(const int* __restrict__ mask)
{
    __shared__ float ks[64 * 64];
    __shared__ float vs[64 * 64];
    __shared__ float gks[GQ * 64];
    __shared__ float gvs[GQ * 64];
    __shared__ unsigned char okc[64];
    __shared__ unsigned char okg[GQ];

    const float* __restrict__ gq = g_scratch + OFF_Q;
    const float* __restrict__ gk = g_scratch + OFF_K;
    const float* __restrict__ gv = g_scratch + OFF_V;
    float* __restrict__ merged   = g_scratch + OFF_MERGED;

    const int blk = blockIdx.x;
    const int n = blk & (NB - 1);
    const int h = (blk >> 5) % NH;
    const int b = blk / (NB * NH);
    const int tid = threadIdx.x;
    const int s = (n << 7) + tid;
    const size_t bh = (size_t)(b * NH + h);

    float q[64];
    {
        const float* qrow = gq + ((bh << 12) + s) * 64;
#pragma unroll
        for (int i = 0; i < 16; i++) {
            float4 t = *(const float4*)(qrow + 4 * i);
            q[4 * i + 0] = t.x; q[4 * i + 1] = t.y;
            q[4 * i + 2] = t.z; q[4 * i + 3] = t.w;
        }
    }

    for (int idx = tid; idx < GQ * 64; idx += 128) {
        const int g = idx >> 6, d = idx & 63;
        gks[idx] = gk[((bh << 12) + g) * 64 + d];
        gvs[idx] = gv[((bh << 12) + g) * 64 + d];
    }
    if (tid < GQ) okg[tid] = (unsigned char)(mask[b * SQ + tid] != 0);

    float m = -1e30f, l = 0.f;
    float acc[64];
#pragma unroll
    for (int i = 0; i < 64; i++) acc[i] = 0.f;

    const int base0 = (n << 7) - 128;
    for (int c = 0; c < 6; c++) {
        const int basec = base0 + (c << 6);
        __syncthreads();
        {
            const int j = tid >> 1, half = tid & 1;
            const int orig = basec + j;
            const bool inr = (orig >= 0) && (orig < SQ);
            float* ksd = ks + j * 64 + (half << 5);
            float* vsd = vs + j * 64 + (half << 5);
            if (inr) {
                const float* kr = gk + ((bh << 12) + orig) * 64 + (half << 5);
                const float* vr = gv + ((bh << 12) + orig) * 64 + (half << 5);
#pragma unroll
                for (int ii = 0; ii < 8; ii++) {
                    *(float4*)(ksd + 4 * ii) = *(const float4*)(kr + 4 * ii);
                    *(float4*)(vsd + 4 * ii) = *(const float4*)(vr + 4 * ii);
                }
            } else {
#pragma unroll
                for (int ii = 0; ii < 8; ii++) {
                    *(float4*)(ksd + 4 * ii) = make_float4(0, 0, 0, 0);
                    *(float4*)(vsd + 4 * ii) = make_float4(0, 0, 0, 0);
                }
            }
            if (half == 0)
                okc[j] = (unsigned char)(inr && orig >= GQ && mask[b * SQ + (inr ? orig : 0)] != 0);
        }
        __syncthreads();

#pragma unroll 1
        for (int j = 0; j < 64; j++) {
            const int orig = basec + j;
            const int rel = orig - s;
            if (!okc[j] || rel > 128 || rel < -128) continue;
            float sc = 0.f;
            const float* kj = ks + j * 64;
#pragma unroll
            for (int dd = 0; dd < 16; dd++) {
                float4 kv = *(const float4*)(kj + 4 * dd);
                sc += q[4 * dd + 0] * kv.x + q[4 * dd + 1] * kv.y
                    + q[4 * dd + 2] * kv.z + q[4 * dd + 3] * kv.w;
            }
            float p;
            if (sc > m) {
                const float corr = __expf(m - sc);
                l *= corr;
#pragma unroll
                for (int dd = 0; dd < 64; dd++) acc[dd] *= corr;
                m = sc;
                p = 1.f;
            } else {
                p = __expf(sc - m);
            }
            l += p;
            const float* vj = vs + j * 64;
#pragma unroll
            for (int dd = 0; dd < 16; dd++) {
                float4 vv = *(const float4*)(vj + 4 * dd);
                acc[4 * dd + 0] += p * vv.x;
                acc[4 * dd + 1] += p * vv.y;
                acc[4 * dd + 2] += p * vv.z;
                acc[4 * dd + 3] += p * vv.w;
            }
        }
    }

#pragma unroll 1
    for (int j = 0; j < GQ; j++) {
        if (!okg[j]) continue;
        float sc = 0.f;
        const float* kj = gks + j * 64;
#pragma unroll
        for (int dd = 0; dd < 16; dd++) {
            float4 kv = *(const float4*)(kj + 4 * dd);
            sc += q[4 * dd + 0] * kv.x + q[4 * dd + 1] * kv.y
                + q[4 * dd + 2] * kv.z + q[4 * dd + 3] * kv.w;
        }
        float p;
        if (sc > m) {
            const float corr = __expf(m - sc);
            l *= corr;
#pragma unroll
            for (int dd = 0; dd < 64; dd++) acc[dd] *= corr;
            m = sc;
            p = 1.f;
        } else {
            p = __expf(sc - m);
        }
        l += p;
        const float* vj = gvs + j * 64;
#pragma unroll
        for (int dd = 0; dd < 16; dd++) {
            float4 vv = *(const float4*)(vj + 4 * dd);
            acc[4 * dd + 0] += p * vv.x;
            acc[4 * dd + 1] += p * vv.y;
            acc[4 * dd + 2] += p * vv.z;
            acc[4 * dd + 3] += p * vv.w;
        }
    }

    const float inv = 1.f / l;
    float* orow = merged + ((size_t)b * SQ + s) * DMODEL + h * 64;
#pragma unroll
    for (int dd = 0; dd < 16; dd++) {
        float4 o;
        o.x = acc[4 * dd + 0] * inv;
        o.y = acc[4 * dd + 1] * inv;
        o.z = acc[4 * dd + 2] * inv;
        o.w = acc[4 * dd + 3] * inv;
        *(float4*)(orow + 4 * dd) = o;
    }
}

// ---------------------------------------------------------------------------
// Global-query attention: rows s < G are replaced by softmax(qg @ kg^T) @ vg.
// One block per (b, h, g). Also computes qg projection inline (tiny).
// ---------------------------------------------------------------------------
__global__ __launch_bounds__(128) void global_attn(const float* __restrict__ x,
                                                   const int* __restrict__ mask,
                                                   const float* __restrict__ Wqg,
                                                   const float* __restrict__ bqg)
{
    __shared__ float xs[DMODEL];
    __shared__ float qs[64];
    __shared__ float part[128];
    __shared__ float sc[SQ];
    __shared__ float red[4];

    const float* __restrict__ kgp = g_scratch + OFF_KG;
    const float* __restrict__ vgp = g_scratch + OFF_VG;
    float* __restrict__ merged    = g_scratch + OFF_MERGED;

    const int blk = blockIdx.x;
    const int g = blk & (GQ - 1);
    const int h = (blk >> 4) % NH;
    const int b = blk / (GQ * NH);
    const int tid = threadIdx.x;
    const size_t bh = (size_t)(b * NH + h);

    for (int i = tid; i < DMODEL; i += 128)
        xs[i] = x[((size_t)b * SQ + g) * DMODEL + i];
    __syncthreads();

    {
        const int d = tid & 63, half = tid >> 6;
        float a = 0.f;
        const float* wp = Wqg + (size_t)(half * 384) * DMODEL + h * 64 + d;
#pragma unroll 4
        for (int i = 0; i < 384; i++) a += xs[half * 384 + i] * wp[(size_t)i * DMODEL];
        part[tid] = a;
    }
    __syncthreads();
    if (tid < 64) qs[tid] = (part[tid] + part[tid + 64] + bqg[h * 64 + tid]) * 0.125f;
    __syncthreads();

    float lmax = -1e30f;
    for (int key = tid; key < SQ; key += 128) {
        const float* kr = kgp + ((bh << 12) + key) * 64;
        float d0 = 0.f;
#pragma unroll
        for (int dd = 0; dd < 16; dd++) {
            float4 kv = *(const float4*)(kr + 4 * dd);
            d0 += qs[4 * dd + 0] * kv.x + qs[4 * dd + 1] * kv.y
                + qs[4 * dd + 2] * kv.z + qs[4 * dd + 3] * kv.w;
        }
        const float v = (mask[b * SQ + key] != 0) ? d0 : -1e9f;
        sc[key] = v;
        lmax = fmaxf(lmax, v);
    }
#pragma unroll
    for (int o = 16; o; o >>= 1) lmax = fmaxf(lmax, __shfl_xor_sync(0xffffffffu, lmax, o));
    if ((tid & 31) == 0) red[tid >> 5] = lmax;
    __syncthreads();
    const float bmax = fmaxf(fmaxf(red[0], red[1]), fmaxf(red[2], red[3]));

    float ls = 0.f;
    for (int key = tid; key < SQ; key += 128) {
        const float e = __expf(sc[key] - bmax);
        sc[key] = e;
        ls += e;
    }
#pragma unroll
    for (int o = 16; o; o >>= 1) ls += __shfl_xor_sync(0xffffffffu, ls, o);
    __syncthreads();
    if ((tid & 31) == 0) red[tid >> 5] = ls;
    __syncthreads();
    const float bsum = red[0] + red[1] + red[2] + red[3];

    {
        const int d = tid & 63, half = tid >> 6;
        float a = 0.f;
        const float* vp = vgp + ((bh << 12) + half * 2048) * 64 + d;
        const float* sp = sc + half * 2048;
#pragma unroll 4
        for (int key = 0; key < 2048; key++) a += sp[key] * vp[(size_t)key * 64];
        part[tid] = a;
    }
    __syncthreads();
    if (tid < 64) {
        const float o = (part[tid] + part[tid + 64]) / bsum;
        merged[((size_t)b * SQ + g) * DMODEL + h * 64 + tid] = o;
    }
}

// ---------------------------------------------------------------------------
extern "C" void kernel_launch(void* const* d_in, const int* in_sizes, int n_in,
                              void* d_out, int out_size)
{
    const float* x    = (const float*)d_in[0];
    const int*   mask = (const int*)d_in[1];
    const float* Wq   = (const float*)d_in[2];
    const float* bq   = (const float*)d_in[3];
    const float* Wk   = (const float*)d_in[4];
    const float* bk   = (const float*)d_in[5];
    const float* Wv   = (const float*)d_in[6];
    const float* bv   = (const float*)d_in[7];
    const float* Wqg  = (const float*)d_in[8];
    const float* bqg  = (const float*)d_in[9];
    const float* Wkg  = (const float*)d_in[10];
    const float* bkg  = (const float*)d_in[11];
    const float* Wvg  = (const float*)d_in[12];
    const float* bvg  = (const float*)d_in[13];
    const float* Wo   = (const float*)d_in[14];
    const float* bo   = (const float*)d_in[15];
    float* out = (float*)d_out;

    PArgs p;
    p.W[0] = Wq;  p.bias[0] = bq;  p.dstOff[0] = OFF_Q;  p.scale[0] = 0.125f;
    p.W[1] = Wk;  p.bias[1] = bk;  p.dstOff[1] = OFF_K;  p.scale[1] = 1.f;
    p.W[2] = Wv;  p.bias[2] = bv;  p.dstOff[2] = OFF_V;  p.scale[2] = 1.f;
    p.W[3] = Wkg; p.bias[3] = bkg; p.dstOff[3] = OFF_KG; p.scale[3] = 1.f;
    p.W[4] = Wvg; p.bias[4] = bvg; p.dstOff[4] = OFF_VG; p.scale[4] = 1.f;

    // 5 projections in one z-batched launch: M=8192, N=768, K=768 (tf32 MMA)
    dim3 gridP(DMODEL / 128, (BATCH * SQ) / 128, 5);
    mma_proj<<<gridP, 256>>>(x, p);

    // local banded attention (+ global-key columns) -> merged
    local_attn<<<BATCH * NH * NB, 128>>>(mask);

    // global-query rows overwrite merged[:, :G, :]
    global_attn<<<BATCH * NH * GQ, 128>>>(x, mask, Wqg, bqg);

    // output projection (tf32 MMA)
    dim3 gridO(DMODEL / 128, (BATCH * SQ) / 128);
    mma_out<<<gridO, 256>>>(Wo, bo, out);
}